// round 12
// baseline (speedup 1.0000x reference)
#include <cuda_runtime.h>
#include <cuda_bf16.h>
#include <cstdint>

#define BCH   10
#define HH    320
#define WW    1024
#define PTS   500
#define DENSE 2000
#define KMEAN 10
#define NPTS  (BCH * PTS)
#define CHUNKS (DENSE / 4)      // 500 int4 chunks per point

// Window: by in [-7,7] (15 rows), bx in [-11,11] (23 cols), padded to 32 cols.
#define WROWS 15
#define WCOLS 23
#define HSLOTS (WROWS * 32)     // 480
#define FULLM 0xFFFFFFFFu

// ONE WARP PER CTA, one point per warp. Validity = 1 LDG instruction (25-lane
// 5x5 window) + 4 shfls + 1 REDUX. Heavy path: stats rows prefetched before
// the bx/by chunk stream; histogram + weighted k-means as before.
__global__ __launch_bounds__(32)
void rsbsp_kernel(const float* __restrict__ disp,
                  const float* __restrict__ fore,
                  const int*   __restrict__ cxs,
                  const int*   __restrict__ cys,
                  const int*   __restrict__ bxs,
                  const int*   __restrict__ bys,
                  float*       __restrict__ out)
{
    __shared__ int hist[HSLOTS];

    const int n    = blockIdx.x;
    const int lane = threadIdx.x;

    const int chan = n / PTS;
    const int cx   = cxs[n];
    const int cy   = cys[n];
    const float* dch = disp + (size_t)chan * (HH * WW);
    const float* fch = fore + (size_t)chan * (HH * WW);
    const int    base = (cy << 10) + cx;          // WW == 1024

    // ---- validity: maxpool3x3(|sobel_x(forepred)|)(cy,cx) > 3.1
    //      && disp(cy,cx) > 0.007.  Centers >= 11 px from all borders.
    // Lane l<25 loads w[l/5][l%5] of the 5x5 forepred window (ONE LDG instr);
    // lane 25 loads the center disp in parallel.
    const int r5 = lane / 5;
    const int c5 = lane - r5 * 5;
    float wv = 0.0f;
    if (lane < 25)
        wv = fch[(size_t)(cy + r5 - 2) * WW + (cx + c5 - 2)];
    float dC = 0.0f;
    if (lane == 25) dC = dch[base];
    dC = __shfl_sync(FULLM, dC, 25);

    // column sums (sobel vertical weights) via lane +-5, then horizontal diff
    // via lane +-1. cs valid on lanes 5..19; centers are lanes with r,c in 1..3.
    const float wup = __shfl_sync(FULLM, wv, (lane + 27) & 31);   // lane-5
    const float wdn = __shfl_sync(FULLM, wv, (lane + 5)  & 31);   // lane+5
    const float cs  = wup + 2.0f * wv + wdn;
    const float csl = __shfl_sync(FULLM, cs, (lane + 31) & 31);   // lane-1
    const float csr = __shfl_sync(FULLM, cs, (lane + 1)  & 31);   // lane+1
    float gg = 0.0f;
    if (r5 >= 1 && r5 <= 3 && c5 >= 1 && c5 <= 3)
        gg = fabsf(csr - csl);
    // gg >= 0 -> float bits are order-monotonic -> single REDUX max
    const float g = __uint_as_float(__reduce_max_sync(FULLM, __float_as_uint(gg)));

    if (!((g > 3.1f) && (dC > 0.007f))) {
        if (lane == 0) { out[2 * n] = 0.0f; out[2 * n + 1] = 0.0f; }
        return;                                   // CTA slot freed immediately
    }

    // ---- heavy path: prefetch stats rows (overlaps the bx/by stream) -------
    float val[WROWS];
    #pragma unroll
    for (int r = 0; r < WROWS; r++)
        val[r] = (lane < WCOLS) ? dch[base + (r - 7) * WW + (lane - 11)] : 0.0f;

    // zero histogram (only heavy CTAs pay this)
    #pragma unroll
    for (int r = 0; r < WROWS; r++) hist[lane + (r << 5)] = 0;
    __syncwarp();

    // ---- histogram of the 2000 samples over the 15x23 window --------------
    const int4* bx4p = (const int4*)(bxs + (size_t)n * DENSE);
    const int4* by4p = (const int4*)(bys + (size_t)n * DENSE);

    #pragma unroll 8
    for (int k = 0; k < 16; k++) {
        const int  c     = lane + (k << 5);
        const bool valid = (k < 15) || (c < CHUNKS);   // compile-time true k<15
        if (valid) {
            const int4 b4 = bx4p[c];
            const int4 y4 = by4p[c];
            // slot = (y+7)*32 + (x+11) = y*32 + x + 235
            atomicAdd(&hist[(y4.x << 5) + b4.x + 235], 1);
            atomicAdd(&hist[(y4.y << 5) + b4.y + 235], 1);
            atomicAdd(&hist[(y4.z << 5) + b4.z + 235], 1);
            atomicAdd(&hist[(y4.w << 5) + b4.w + 235], 1);
        }
    }
    __syncwarp();

    // ---- weighted stats over the 15x23 window -----------------------------
    int   cnti[WROWS];
    float prod[WROWS];
    unsigned mxu = 0u, mnu = 0x7f800000u;         // disp >= 0: bit-monotonic
    float stot = 0.0f;
    #pragma unroll
    for (int r = 0; r < WROWS; r++) {
        const int cnt = hist[lane + (r << 5)];
        cnti[r] = cnt;
        prod[r] = val[r] * (float)cnt;
        stot   += prod[r];
        if (cnt > 0) {
            const unsigned vb = __float_as_uint(val[r]);
            mxu = mxu > vb ? mxu : vb;
            mnu = mnu < vb ? mnu : vb;
        }
    }
    mxu = __reduce_max_sync(FULLM, mxu);
    mnu = __reduce_min_sync(FULLM, mnu);
    #pragma unroll
    for (int o = 16; o; o >>= 1) stot += __shfl_xor_sync(FULLM, stot, o);

    // ---- weighted 2-cluster 1-D k-means over <=345 unique values ----------
    // kL > kS => |s-kL|<=|s-kS| <=> s >= (kL+kS)/2 (midpoint tie -> large,
    // matching dl<=ds). Threshold acts on val only, so weighted sums equal the
    // per-sample sums exactly (same partition). Bitwise fixed point => the
    // remaining reference iterations are no-ops -> exact early exit.
    float kL = __uint_as_float(mxu), kS = __uint_as_float(mnu);
    float lastCnt = 0.0f;
    #pragma unroll 1
    for (int it = 0; it < KMEAN; it++) {
        const float mid = 0.5f * (kL + kS);
        float sumL = 0.0f;
        int   ci   = 0;
        #pragma unroll
        for (int r = 0; r < WROWS; r++) {
            if (val[r] >= mid) { sumL += prod[r]; ci += cnti[r]; }
        }
        #pragma unroll
        for (int o = 16; o; o >>= 1) sumL += __shfl_xor_sync(FULLM, sumL, o);
        const float cntL = (float)__reduce_add_sync(FULLM, ci);

        const float nkL = __fdividef(sumL, cntL);
        const float nkS = __fdividef(stot - sumL, (float)DENSE - cntL);
        lastCnt = cntL;
        const bool conv = (nkL == kL) && (nkS == kS);
        kL = nkL; kS = nkS;
        if (conv) break;
    }

    const bool keep = ((kL - kS) > 0.005f) && (lastCnt > 5.0f);
    if (lane == 0) {
        const float kf = keep ? 1.0f : 0.0f;
        out[2 * n]     = kL * kf;
        out[2 * n + 1] = kS * kf;
    }
}

extern "C" void kernel_launch(void* const* d_in, const int* in_sizes, int n_in,
                              void* d_out, int out_size)
{
    const float* disp = (const float*)d_in[0];
    const float* fore = (const float*)d_in[1];
    const int*   cxs  = (const int*)  d_in[2];
    const int*   cys  = (const int*)  d_in[3];
    const int*   bxs  = (const int*)  d_in[4];
    const int*   bys  = (const int*)  d_in[5];
    float*       out  = (float*)d_out;

    rsbsp_kernel<<<NPTS, 32>>>(disp, fore, cxs, cys, bxs, bys, out);
}